// round 1
// baseline (speedup 1.0000x reference)
#include <cuda_runtime.h>

#define BB 16
#define NN 2000
#define EE 8000
#define DD 64
#define XROWS (EE + NN)   // 10000 rows per batch in x

// ---------------- scratch (device globals; no allocation) ----------------
__device__ __align__(16) float g_h [BB * NN * DD];   // h = nodes@W_node + b_node
__device__ __align__(16) float g_A [BB * NN * DD];   // h @ W1
__device__ __align__(16) float g_C [BB * NN * DD];   // h @ W3
__device__ __align__(16) float g_Bf[BB * EE * DD];   // edges @ (W_edge@W2)
__device__ __align__(16) float g_M [DD * DD];        // W_edge @ W2
__device__ float g_logits[BB * 16000];
__device__ float g_alpha [BB * 16000];
__device__ float g_stats [BB * 2];                   // {max, 1/sumexp} per batch
__device__ int   g_start [NN + 1];                   // edge range per src node

// ---------------- K0: M = W_edge @ W2 (64x64x64, one block) ----------------
__global__ void mm64_kernel(const float* __restrict__ A, const float* __restrict__ B)
{
    __shared__ float sa[4096], sb[4096];
    int tid = threadIdx.x;
    for (int i = tid; i < 4096; i += 256) { sa[i] = A[i]; sb[i] = B[i]; }
    __syncthreads();
    for (int o = tid; o < 4096; o += 256) {
        int i = o >> 6, j = o & 63;
        float s = 0.f;
        #pragma unroll 16
        for (int k = 0; k < 64; k++) s += sa[i * 64 + k] * sb[k * 64 + j];
        g_M[o] = s;
    }
}

// ---------------- Kr: per-src-node edge ranges (src is sorted) ----------------
__global__ void ranges_kernel(const int* __restrict__ src, int E2)
{
    int n = blockIdx.x * blockDim.x + threadIdx.x;
    if (n > NN) return;
    int lo = 0, hi = E2;
    while (lo < hi) { int m = (lo + hi) >> 1; if (src[m] < n) lo = m + 1; else hi = m; }
    g_start[n] = lo;
}

// ---------------- generic 64-col GEMM: Y[r][c] = sum_k X[map(r)][k]*W[k][c] (+bias) ----
// map(r): sb = r / batchRows; srcRow = sb*srcStride + srcOffset + (r - sb*batchRows)
// Tile: 64 rows x 64 cols per block, 256 threads, 4x4 register tile.
__global__ void gemm64_kernel(const float* __restrict__ X, const float* __restrict__ W,
                              const float* __restrict__ bias, float* __restrict__ Y,
                              int batchRows, int srcStride, int srcOffset)
{
    __shared__ float xt[64][68];   // transposed X tile: xt[k][r], padded stride (16B aligned)
    __shared__ float ws[64][64];   // ws[k][c]
    const int tid = threadIdx.x;
    const int rowBase = blockIdx.x * 64;

    #pragma unroll
    for (int i = 0; i < 4; i++) {
        int idx = tid + i * 256;          // float4 index within tile (0..1023)
        int r   = idx >> 4;               // 16 float4 per row
        int c4  = idx & 15;
        int gr  = rowBase + r;
        int sb  = gr / batchRows;
        long srow = (long)sb * srcStride + srcOffset + (gr - sb * batchRows);
        float4 v = ((const float4*)X)[srow * 16 + c4];
        xt[c4 * 4 + 0][r] = v.x;
        xt[c4 * 4 + 1][r] = v.y;
        xt[c4 * 4 + 2][r] = v.z;
        xt[c4 * 4 + 3][r] = v.w;
    }
    #pragma unroll
    for (int i = 0; i < 4; i++) {
        int idx = tid + i * 256;
        ((float4*)&ws[0][0])[idx] = ((const float4*)W)[idx];
    }
    __syncthreads();

    const int tr = (tid >> 4) << 2;   // row offset 0..60
    const int tc = (tid & 15) << 2;   // col offset 0..60
    float acc[4][4] = {};
    #pragma unroll 8
    for (int k = 0; k < 64; k++) {
        float4 a = *(const float4*)&xt[k][tr];
        float4 b = *(const float4*)&ws[k][tc];
        acc[0][0] += a.x * b.x; acc[0][1] += a.x * b.y; acc[0][2] += a.x * b.z; acc[0][3] += a.x * b.w;
        acc[1][0] += a.y * b.x; acc[1][1] += a.y * b.y; acc[1][2] += a.y * b.z; acc[1][3] += a.y * b.w;
        acc[2][0] += a.z * b.x; acc[2][1] += a.z * b.y; acc[2][2] += a.z * b.z; acc[2][3] += a.z * b.w;
        acc[3][0] += a.w * b.x; acc[3][1] += a.w * b.y; acc[3][2] += a.w * b.z; acc[3][3] += a.w * b.w;
    }

    float4 bb = bias ? ((const float4*)bias)[tc >> 2] : make_float4(0.f, 0.f, 0.f, 0.f);
    #pragma unroll
    for (int i = 0; i < 4; i++) {
        float4 o = make_float4(acc[i][0] + bb.x, acc[i][1] + bb.y,
                               acc[i][2] + bb.z, acc[i][3] + bb.w);
        ((float4*)Y)[(long)(rowBase + tr + i) * 16 + (tc >> 2)] = o;
    }
}

// ---------------- K3: per-edge combine + leaky_relu + attention logit ----------------
// one warp per (b, e); lane handles dims {2*lane, 2*lane+1}
__global__ void edge_kernel(const float* __restrict__ b_comb,
                            const float* __restrict__ w_attn,
                            const int* __restrict__ src,
                            const int* __restrict__ dst,
                            const int* __restrict__ eidx,
                            float* __restrict__ out, int E2)
{
    int gw   = (blockIdx.x * blockDim.x + threadIdx.x) >> 5;
    int lane = threadIdx.x & 31;
    if (gw >= BB * E2) return;
    int b = gw / E2;
    int e = gw - b * E2;
    int s = src[e], t = dst[e], q = eidx[e];

    float2 va = ((const float2*)(g_A  + ((long)b * NN + s) * DD))[lane];
    float2 vf = ((const float2*)(g_Bf + ((long)b * EE + q) * DD))[lane];
    float2 vc = ((const float2*)(g_C  + ((long)b * NN + t) * DD))[lane];
    float2 vb = ((const float2*)b_comb)[lane];

    float v0 = va.x + vf.x + vc.x + vb.x;
    float v1 = va.y + vf.y + vc.y + vb.y;
    v0 = v0 > 0.f ? v0 : 0.01f * v0;
    v1 = v1 > 0.f ? v1 : 0.01f * v1;

    ((float2*)(out + ((long)b * (E2 + NN) + e) * DD))[lane] = make_float2(v0, v1);

    float2 w = ((const float2*)w_attn)[lane];
    float dot = v0 * w.x + v1 * w.y;
    #pragma unroll
    for (int o = 16; o; o >>= 1) dot += __shfl_xor_sync(0xffffffffu, dot, o);
    if (lane == 0) g_logits[gw] = dot;
}

// ---------------- K4: per-batch softmax stats over E2 logits ----------------
__global__ void softmax_stats_kernel(int E2)
{
    __shared__ float red[256];
    int b = blockIdx.x, tid = threadIdx.x;
    const float* L = g_logits + (long)b * E2;
    float mx = -1e30f;
    for (int i = tid; i < E2; i += 256) mx = fmaxf(mx, L[i]);
    red[tid] = mx; __syncthreads();
    for (int s = 128; s > 0; s >>= 1) {
        if (tid < s) red[tid] = fmaxf(red[tid], red[tid + s]);
        __syncthreads();
    }
    mx = red[0]; __syncthreads();
    float sm = 0.f;
    for (int i = tid; i < E2; i += 256) sm += expf(L[i] - mx);
    red[tid] = sm; __syncthreads();
    for (int s = 128; s > 0; s >>= 1) {
        if (tid < s) red[tid] += red[tid + s];
        __syncthreads();
    }
    if (tid == 0) { g_stats[2 * b] = mx; g_stats[2 * b + 1] = 1.0f / red[0]; }
}

// ---------------- K4b: alpha = exp(logit - max) / sum ----------------
__global__ void alpha_kernel(int total, int E2)
{
    int i = blockIdx.x * 256 + threadIdx.x;
    if (i >= total) return;
    int b = i / E2;
    g_alpha[i] = expf(g_logits[i] - g_stats[2 * b]) * g_stats[2 * b + 1];
}

// ---------------- K5: segmented aggregation h_out[b,n] = sum alpha_e * h[b,dst_e] ----
__global__ void aggregate_kernel(const int* __restrict__ dst,
                                 float* __restrict__ out, int E2)
{
    int bn = blockIdx.x;
    int b = bn / NN, n = bn - b * NN;
    int d = threadIdx.x;  // 64
    int s0 = g_start[n], s1 = g_start[n + 1];
    const float* hb = g_h + (long)b * NN * DD;
    const float* al = g_alpha + (long)b * E2;
    float acc = 0.f;
    for (int i = s0; i < s1; i++)
        acc += al[i] * hb[dst[i] * DD + d];
    out[((long)b * (E2 + NN) + E2 + n) * DD + d] = acc;
}

// ---------------- launch ----------------
extern "C" void kernel_launch(void* const* d_in, const int* in_sizes, int n_in,
                              void* d_out, int out_size)
{
    const float* x      = (const float*)d_in[0];
    const float* W_edge = (const float*)d_in[1];
    const float* W_node = (const float*)d_in[2];
    const float* b_node = (const float*)d_in[3];
    const float* W_comb = (const float*)d_in[4];
    const float* b_comb = (const float*)d_in[5];
    const float* w_attn = (const float*)d_in[6];
    const int*   src    = (const int*)d_in[7];
    const int*   dst    = (const int*)d_in[8];
    const int*   eidx   = (const int*)d_in[9];
    const int    E2     = in_sizes[7];       // directed edge count (16000)
    float* out = (float*)d_out;

    void *ph, *pA, *pC, *pBf, *pM;
    cudaGetSymbolAddress(&ph,  g_h);
    cudaGetSymbolAddress(&pA,  g_A);
    cudaGetSymbolAddress(&pC,  g_C);
    cudaGetSymbolAddress(&pBf, g_Bf);
    cudaGetSymbolAddress(&pM,  g_M);

    // M = W_edge @ W2   (W2 = W_comb rows 64..127)
    mm64_kernel<<<1, 256>>>(W_edge, W_comb + 64 * 64);

    // per-node edge ranges (src sorted)
    ranges_kernel<<<(NN + 1 + 255) / 256, 256>>>(src, E2);

    // h = nodes @ W_node + b_node       (nodes at x[:, EE:], batch stride XROWS)
    gemm64_kernel<<<BB * NN / 64, 256>>>(x, W_node, b_node, (float*)ph, NN, XROWS, EE);
    // A = h @ W1
    gemm64_kernel<<<BB * NN / 64, 256>>>((const float*)ph, W_comb, nullptr, (float*)pA, NN, NN, 0);
    // C = h @ W3
    gemm64_kernel<<<BB * NN / 64, 256>>>((const float*)ph, W_comb + 2 * 64 * 64, nullptr, (float*)pC, NN, NN, 0);
    // Bf = edges @ M                    (edges at x[:, :EE], batch stride XROWS)
    gemm64_kernel<<<BB * EE / 64, 256>>>(x, (const float*)pM, nullptr, (float*)pBf, EE, XROWS, 0);

    // per-edge combine + logits (one warp per (b,e))
    long warps = (long)BB * E2;
    edge_kernel<<<(unsigned)((warps * 32 + 255) / 256), 256>>>(b_comb, w_attn, src, dst, eidx, out, E2);

    // softmax over edges per batch
    softmax_stats_kernel<<<BB, 256>>>(E2);
    alpha_kernel<<<(BB * E2 + 255) / 256, 256>>>(BB * E2, E2);

    // h_out aggregation (segmented, deterministic, no atomics)
    aggregate_kernel<<<BB * NN, 64>>>(dst, out, E2);
}

// round 2
// speedup vs baseline: 1.0235x; 1.0235x over previous
#include <cuda_runtime.h>

#define BB 16
#define NN 2000
#define EE 8000
#define DD 64
#define XROWS (EE + NN)
#define E2MAX 16000

// ---------------- scratch (device globals) ----------------
__device__ __align__(16) float g_h [BB * NN * DD];
__device__ __align__(16) float g_A [BB * NN * DD];
__device__ __align__(16) float g_C [BB * NN * DD];
__device__ __align__(16) float g_Bf[BB * EE * DD];
__device__ __align__(16) float g_M [DD * DD];     // W_edge@W2
__device__ __align__(16) float g_WA[DD * DD];     // W_node@W1
__device__ __align__(16) float g_WC[DD * DD];     // W_node@W3
__device__ __align__(16) float g_bA[DD];          // b_node@W1
__device__ __align__(16) float g_bC[DD];          // b_node@W3
__device__ float g_expl[BB * E2MAX];
__device__ float g_psum[BB * (E2MAX / 16)];
__device__ float g_inv [BB];
__device__ int   g_start[NN + 1];

// ---------------- prep: fold weights + edge ranges (5 blocks) ----------------
__device__ void mm64_dev(const float* __restrict__ A, const float* __restrict__ B,
                         float* __restrict__ O)
{
    __shared__ float sa[4096], sb[4096];
    int tid = threadIdx.x;
    for (int i = tid; i < 4096; i += 256) { sa[i] = A[i]; sb[i] = B[i]; }
    __syncthreads();
    for (int o = tid; o < 4096; o += 256) {
        int i = o >> 6, j = o & 63;
        float s = 0.f;
        #pragma unroll 16
        for (int k = 0; k < 64; k++) s += sa[i * 64 + k] * sb[k * 64 + j];
        O[o] = s;
    }
}

__global__ void prep_kernel(const float* __restrict__ W_edge,
                            const float* __restrict__ W_node,
                            const float* __restrict__ b_node,
                            const float* __restrict__ W_comb,
                            const int* __restrict__ src, int E2)
{
    int blk = blockIdx.x, tid = threadIdx.x;
    if (blk == 0)      mm64_dev(W_edge, W_comb + 64 * 64, g_M);   // W2
    else if (blk == 1) mm64_dev(W_node, W_comb,           g_WA);  // W1
    else if (blk == 2) mm64_dev(W_node, W_comb + 128 * 64, g_WC); // W3
    else if (blk == 3) {
        if (tid < 128) {
            int c = tid & 63;
            const float* W = (tid < 64) ? W_comb : (W_comb + 128 * 64);
            float s = 0.f;
            #pragma unroll 16
            for (int k = 0; k < 64; k++) s += b_node[k] * W[k * 64 + c];
            if (tid < 64) g_bA[c] = s; else g_bC[c] = s;
        }
    } else {
        for (int n = tid; n <= NN; n += 256) {
            int lo = 0, hi = E2;
            while (lo < hi) { int m = (lo + hi) >> 1; if (src[m] < n) lo = m + 1; else hi = m; }
            g_start[n] = lo;
        }
    }
}

// ---------------- unified GEMM: 128 rows x 64 cols per block, 4x8 per thread ----
// sets: 0:h 1:A 2:C (node rows, 250 blocks each)  3:Bf (edge rows, 1000 blocks)
#define XT_S 132
__global__ void __launch_bounds__(256, 4)
gemm_kernel(const float* __restrict__ X,
            const float* __restrict__ W_node, const float* __restrict__ b_node)
{
    extern __shared__ float sm[];
    float* xt = sm;              // [64][132] transposed X tile
    float* ws = sm + 64 * XT_S;  // [64][64]

    int bid = blockIdx.x;
    int set, rb;
    if (bid < 750) { set = bid / 250; rb = bid - set * 250; }
    else           { set = 3;         rb = bid - 750; }

    const float* Wp; const float* bp; float* Yp;
    if (set == 0)      { Wp = W_node; bp = b_node; Yp = g_h; }
    else if (set == 1) { Wp = g_WA;   bp = g_bA;   Yp = g_A; }
    else if (set == 2) { Wp = g_WC;   bp = g_bC;   Yp = g_C; }
    else               { Wp = g_M;    bp = nullptr; Yp = g_Bf; }
    const int bR  = (set < 3) ? NN : EE;
    const int off = (set < 3) ? EE : 0;

    const int tid = threadIdx.x;
    const int rowBase = rb * 128;

    // load X tile (128 rows x 64 cols) transposed into xt[k][r]
    #pragma unroll
    for (int i = 0; i < 8; i++) {
        int idx = tid + i * 256;        // 0..2047 float4 slots
        int r   = idx >> 4;             // 0..127
        int c4  = idx & 15;
        int gr  = rowBase + r;
        int sb  = gr / bR;
        long srow = (long)sb * XROWS + off + (gr - sb * bR);
        float4 v = ((const float4*)X)[srow * 16 + c4];
        xt[(c4 * 4 + 0) * XT_S + r] = v.x;
        xt[(c4 * 4 + 1) * XT_S + r] = v.y;
        xt[(c4 * 4 + 2) * XT_S + r] = v.z;
        xt[(c4 * 4 + 3) * XT_S + r] = v.w;
    }
    #pragma unroll
    for (int i = 0; i < 4; i++) {
        int idx = tid + i * 256;
        ((float4*)ws)[idx] = ((const float4*)Wp)[idx];
    }
    __syncthreads();

    const int tr = (tid >> 3) << 2;   // row offset 0..124 (step 4)
    const int tc = (tid & 7) << 3;    // col offset 0..56  (step 8)

    float acc[4][8];
    #pragma unroll
    for (int i = 0; i < 4; i++)
        #pragma unroll
        for (int j = 0; j < 8; j++) acc[i][j] = 0.f;

    #pragma unroll 16
    for (int k = 0; k < 64; k++) {
        float4 a  = *(const float4*)(xt + k * XT_S + tr);
        float4 b0 = *(const float4*)(ws + k * 64 + tc);
        float4 b1 = *(const float4*)(ws + k * 64 + tc + 4);
        float av[4] = {a.x, a.y, a.z, a.w};
        float bv[8] = {b0.x, b0.y, b0.z, b0.w, b1.x, b1.y, b1.z, b1.w};
        #pragma unroll
        for (int i = 0; i < 4; i++)
            #pragma unroll
            for (int j = 0; j < 8; j++)
                acc[i][j] += av[i] * bv[j];
    }

    float bb[8];
    #pragma unroll
    for (int j = 0; j < 8; j++) bb[j] = bp ? bp[tc + j] : 0.f;

    #pragma unroll
    for (int i = 0; i < 4; i++) {
        long row = rowBase + tr + i;
        float4 o0 = make_float4(acc[i][0] + bb[0], acc[i][1] + bb[1],
                                acc[i][2] + bb[2], acc[i][3] + bb[3]);
        float4 o1 = make_float4(acc[i][4] + bb[4], acc[i][5] + bb[5],
                                acc[i][6] + bb[6], acc[i][7] + bb[7]);
        ((float4*)Yp)[row * 16 + (tc >> 2)]     = o0;
        ((float4*)Yp)[row * 16 + (tc >> 2) + 1] = o1;
    }
}

// ---------------- edge: combine + lrelu + exp(logit) + block partial sum ----
// one warp per (b,e); 512-thread blocks = 16 warps (same batch: 16 | E2)
__global__ void edge_kernel(const float* __restrict__ b_comb,
                            const float* __restrict__ w_attn,
                            const int* __restrict__ src,
                            const int* __restrict__ dst,
                            const int* __restrict__ eidx,
                            float* __restrict__ out, int E2)
{
    __shared__ float wred[16];
    int warp = threadIdx.x >> 5, lane = threadIdx.x & 31;
    int gw = blockIdx.x * 16 + warp;
    int b = gw / E2;
    int e = gw - b * E2;
    int s = src[e], t = dst[e], q = eidx[e];

    float2 va = ((const float2*)(g_A  + ((long)b * NN + s) * DD))[lane];
    float2 vf = ((const float2*)(g_Bf + ((long)b * EE + q) * DD))[lane];
    float2 vc = ((const float2*)(g_C  + ((long)b * NN + t) * DD))[lane];
    float2 vb = ((const float2*)b_comb)[lane];

    float v0 = va.x + vf.x + vc.x + vb.x;
    float v1 = va.y + vf.y + vc.y + vb.y;
    v0 = v0 > 0.f ? v0 : 0.01f * v0;
    v1 = v1 > 0.f ? v1 : 0.01f * v1;

    ((float2*)(out + ((long)b * (E2 + NN) + e) * DD))[lane] = make_float2(v0, v1);

    float2 w = ((const float2*)w_attn)[lane];
    float dot = v0 * w.x + v1 * w.y;
    #pragma unroll
    for (int o = 16; o; o >>= 1) dot += __shfl_xor_sync(0xffffffffu, dot, o);

    float ev = expf(dot);      // logits are tiny; no max-shift needed
    if (lane == 0) { g_expl[gw] = ev; wred[warp] = ev; }
    __syncthreads();
    if (threadIdx.x < 16) {
        float v = wred[threadIdx.x];
        #pragma unroll
        for (int o = 8; o; o >>= 1) v += __shfl_xor_sync(0xffffu, v, o);
        if (threadIdx.x == 0) g_psum[blockIdx.x] = v;
    }
}

// ---------------- per-batch sum of partials -> 1/sum ----------------
__global__ void sum_kernel(int pb)   // pb = blocks per batch in edge_kernel
{
    __shared__ float red[256];
    int b = blockIdx.x, tid = threadIdx.x;
    float s = 0.f;
    for (int j = tid; j < pb; j += 256) s += g_psum[b * pb + j];
    red[tid] = s; __syncthreads();
    for (int st = 128; st > 0; st >>= 1) {
        if (tid < st) red[tid] += red[tid + st];
        __syncthreads();
    }
    if (tid == 0) g_inv[b] = 1.0f / red[0];
}

// ---------------- segmented aggregation, alpha inline ----------------
// one warp per (b,n); 256-thread blocks = 8 warps
__global__ void aggregate_kernel(const int* __restrict__ dst,
                                 float* __restrict__ out, int E2)
{
    int warp = threadIdx.x >> 5, lane = threadIdx.x & 31;
    int gw = blockIdx.x * 8 + warp;
    int b = gw / NN, n = gw - b * NN;
    int s0 = g_start[n], s1 = g_start[n + 1];
    float inv = g_inv[b];
    const float2* hb = (const float2*)(g_h + (long)b * NN * DD);
    const float*  ex = g_expl + (long)b * E2;
    float2 acc = make_float2(0.f, 0.f);
    for (int i = s0; i < s1; i++) {
        float a = ex[i] * inv;
        float2 hv = hb[(long)dst[i] * 32 + lane];
        acc.x += a * hv.x;
        acc.y += a * hv.y;
    }
    ((float2*)(out + ((long)b * (E2 + NN) + E2 + n) * DD))[lane] = acc;
}

// ---------------- launch ----------------
extern "C" void kernel_launch(void* const* d_in, const int* in_sizes, int n_in,
                              void* d_out, int out_size)
{
    const float* x      = (const float*)d_in[0];
    const float* W_edge = (const float*)d_in[1];
    const float* W_node = (const float*)d_in[2];
    const float* b_node = (const float*)d_in[3];
    const float* W_comb = (const float*)d_in[4];
    const float* b_comb = (const float*)d_in[5];
    const float* w_attn = (const float*)d_in[6];
    const int*   src    = (const int*)d_in[7];
    const int*   dst    = (const int*)d_in[8];
    const int*   eidx   = (const int*)d_in[9];
    const int    E2     = in_sizes[7];   // 16000
    float* out = (float*)d_out;

    static int smem_set = 0;
    const int gemm_smem = (64 * XT_S + 64 * 64) * (int)sizeof(float);  // 50176
    cudaFuncSetAttribute(gemm_kernel, cudaFuncAttributeMaxDynamicSharedMemorySize, gemm_smem);
    (void)smem_set;

    prep_kernel<<<5, 256>>>(W_edge, W_node, b_node, W_comb, src, E2);

    gemm_kernel<<<1750, 256, gemm_smem>>>(x, W_node, b_node);

    edge_kernel<<<BB * E2 / 16, 512>>>(b_comb, w_attn, src, dst, eidx, out, E2);

    sum_kernel<<<BB, 256>>>(E2 / 16);

    aggregate_kernel<<<BB * NN / 8, 256>>>(dst, out, E2);
}

// round 6
// speedup vs baseline: 1.3432x; 1.3123x over previous
#include <cuda_runtime.h>
#include <cstdint>

#define BB 16
#define NN 2000
#define EE 8000
#define DD 64
#define XROWS 10000
#define E2MAX 16000

// ---------------- scratch (device globals) ----------------
__device__ __align__(16) float g_h [BB * NN * DD];
__device__ __align__(16) float g_A [BB * NN * DD];
__device__ __align__(16) float g_C [BB * NN * DD];
__device__ __align__(16) float g_Bf[BB * EE * DD];
__device__ __align__(16) float g_M [DD * DD];     // W_edge@W2
__device__ __align__(16) float g_WA[DD * DD];     // W_node@W1
__device__ __align__(16) float g_WC[DD * DD];     // W_node@W3
__device__ __align__(16) float g_bA[DD];
__device__ __align__(16) float g_bC[DD];
__device__ float g_expl[BB * E2MAX];
__device__ float g_psum[BB * (E2MAX / 16)];
__device__ float g_inv [BB];
__device__ int   g_start[NN + 1];

__device__ __forceinline__ uint32_t f2tf(float f) {
    uint32_t r; asm("cvt.rna.tf32.f32 %0, %1;" : "=r"(r) : "f"(f)); return r;
}

// ---------------- prep kernels ----------------
__device__ void mm64_dev(const float* __restrict__ A, const float* __restrict__ B,
                         float* __restrict__ O)
{
    __shared__ float sa[4096], sb[4096];
    int tid = threadIdx.x;
    for (int i = tid; i < 4096; i += 256) { sa[i] = A[i]; sb[i] = B[i]; }
    __syncthreads();
    for (int o = tid; o < 4096; o += 256) {
        int i = o >> 6, j = o & 63;
        float s = 0.f;
        #pragma unroll 16
        for (int k = 0; k < 64; k++) s += sa[i * 64 + k] * sb[k * 64 + j];
        O[o] = s;
    }
}

__global__ void prep_mm_kernel(const float* __restrict__ W_edge,
                               const float* __restrict__ W_node,
                               const float* __restrict__ W_comb)
{
    if (blockIdx.x == 0)      mm64_dev(W_edge, W_comb + 64 * 64,  g_M);
    else if (blockIdx.x == 1) mm64_dev(W_node, W_comb,            g_WA);
    else                      mm64_dev(W_node, W_comb + 128 * 64, g_WC);
}

__global__ void prep_bias_kernel(const float* __restrict__ b_node,
                                 const float* __restrict__ W_comb)
{
    int tid = threadIdx.x;
    if (tid < 128) {
        int c = tid & 63;
        const float* W = (tid < 64) ? W_comb : (W_comb + 128 * 64);
        float s = 0.f;
        #pragma unroll 16
        for (int k = 0; k < 64; k++) s += b_node[k] * W[k * 64 + c];
        if (tid < 64) g_bA[c] = s; else g_bC[c] = s;
    }
}

__global__ void ranges_kernel(const int* __restrict__ src, int E2)
{
    int n = blockIdx.x * blockDim.x + threadIdx.x;
    if (n > NN) return;
    int lo = 0, hi = E2;
    while (lo < hi) { int m = (lo + hi) >> 1; if (src[m] < n) lo = m + 1; else hi = m; }
    g_start[n] = lo;
}

// ---------------- tf32 mma.sync GEMM: 128x64 tile, K=64 ----------------
// sets: 0:h 1:A 2:C (250 blocks each)  3:Bf (1000 blocks)
// Per warp: 16 rows x 64 cols = 8 n-tiles x 8 k-steps of m16n8k8.
#define XS_S 68
#define SMEM_GEMM ((128 * XS_S + 64 * XS_S) * 4)   // 52224 bytes

__global__ void __launch_bounds__(256)
gemm_mma_kernel(const float* __restrict__ X,
                const float* __restrict__ W_node, const float* __restrict__ b_node)
{
    extern __shared__ uint32_t sm[];
    uint32_t* xs = sm;               // [128][68] tf32 bits of X tile
    uint32_t* ws = sm + 128 * XS_S;  // [64][68]  tf32 bits of W (k-major)

    int bid = blockIdx.x, set, rb;
    if (bid < 750) { set = bid / 250; rb = bid - set * 250; }
    else           { set = 3;         rb = bid - 750; }
    const float* Wp; const float* bp; float* Yp;
    if (set == 0)      { Wp = W_node; bp = b_node; Yp = g_h; }
    else if (set == 1) { Wp = g_WA;   bp = g_bA;   Yp = g_A; }
    else if (set == 2) { Wp = g_WC;   bp = g_bC;   Yp = g_C; }
    else               { Wp = g_M;    bp = nullptr; Yp = g_Bf; }
    const int bR  = (set < 3) ? NN : EE;
    const int off = (set < 3) ? EE : 0;
    const int rowBase = rb * 128;

    const int tid = threadIdx.x;

    // stage X tile (128x64) -> tf32
    #pragma unroll
    for (int i = 0; i < 8; i++) {
        int idx = tid + i * 256;        // 0..2047 float4 slots
        int r   = idx >> 4;
        int c4  = idx & 15;
        int gr  = rowBase + r;
        int sb  = gr / bR;
        long srow = (long)sb * XROWS + off + (gr - sb * bR);
        float4 v = ((const float4*)X)[srow * 16 + c4];
        uint4 u;
        u.x = f2tf(v.x); u.y = f2tf(v.y); u.z = f2tf(v.z); u.w = f2tf(v.w);
        *(uint4*)&xs[r * XS_S + c4 * 4] = u;
    }
    // stage W (64x64, k-major) -> tf32
    #pragma unroll
    for (int i = 0; i < 4; i++) {
        int idx = tid + i * 256;        // 0..1023 float4 slots
        int k   = idx >> 4;
        int c4  = idx & 15;
        float4 v = ((const float4*)Wp)[idx];
        uint4 u;
        u.x = f2tf(v.x); u.y = f2tf(v.y); u.z = f2tf(v.z); u.w = f2tf(v.w);
        *(uint4*)&ws[k * XS_S + c4 * 4] = u;
    }
    __syncthreads();

    const int warp = tid >> 5, lane = tid & 31;
    const int g = lane >> 2, t = lane & 3;
    const int r0 = warp * 16;

    float acc[8][4];
    #pragma unroll
    for (int nt = 0; nt < 8; nt++)
        #pragma unroll
        for (int j = 0; j < 4; j++) acc[nt][j] = 0.f;

    #pragma unroll
    for (int ks = 0; ks < 8; ks++) {
        const int k8 = ks * 8;
        uint32_t a0 = xs[(r0 + g)     * XS_S + k8 + t];
        uint32_t a1 = xs[(r0 + g + 8) * XS_S + k8 + t];
        uint32_t a2 = xs[(r0 + g)     * XS_S + k8 + t + 4];
        uint32_t a3 = xs[(r0 + g + 8) * XS_S + k8 + t + 4];
        #pragma unroll
        for (int nt = 0; nt < 8; nt++) {
            uint32_t b0 = ws[(k8 + t)     * XS_S + nt * 8 + g];
            uint32_t b1 = ws[(k8 + t + 4) * XS_S + nt * 8 + g];
            asm volatile(
                "mma.sync.aligned.m16n8k8.row.col.f32.tf32.tf32.f32 "
                "{%0,%1,%2,%3}, {%4,%5,%6,%7}, {%8,%9}, {%0,%1,%2,%3};"
                : "+f"(acc[nt][0]), "+f"(acc[nt][1]), "+f"(acc[nt][2]), "+f"(acc[nt][3])
                : "r"(a0), "r"(a1), "r"(a2), "r"(a3), "r"(b0), "r"(b1));
        }
    }

    // epilogue: lane holds rows {r0+g, r0+g+8}, cols {nt*8+2t, nt*8+2t+1}
    long row0 = rowBase + r0 + g;
    long row1 = row0 + 8;
    #pragma unroll
    for (int nt = 0; nt < 8; nt++) {
        int c = nt * 8 + 2 * t;
        float bx = bp ? __ldg(bp + c)     : 0.f;
        float by = bp ? __ldg(bp + c + 1) : 0.f;
        ((float2*)(Yp + row0 * 64 + c))[0] = make_float2(acc[nt][0] + bx, acc[nt][1] + by);
        ((float2*)(Yp + row1 * 64 + c))[0] = make_float2(acc[nt][2] + bx, acc[nt][3] + by);
    }
}

// ---------------- edge: combine + lrelu + exp(logit) + partial sums ----------------
__global__ void edge_kernel(const float* __restrict__ b_comb,
                            const float* __restrict__ w_attn,
                            const int* __restrict__ src,
                            const int* __restrict__ dst,
                            const int* __restrict__ eidx,
                            float* __restrict__ out, int E2)
{
    __shared__ float wred[16];
    int warp = threadIdx.x >> 5, lane = threadIdx.x & 31;
    int gw = blockIdx.x * 16 + warp;
    int b = gw / E2;
    int e = gw - b * E2;
    int s = src[e], t = dst[e], q = eidx[e];

    float2 va = ((const float2*)(g_A  + ((long)b * NN + s) * DD))[lane];
    float2 vf = ((const float2*)(g_Bf + ((long)b * EE + q) * DD))[lane];
    float2 vc = ((const float2*)(g_C  + ((long)b * NN + t) * DD))[lane];
    float2 vb = ((const float2*)b_comb)[lane];

    float v0 = va.x + vf.x + vc.x + vb.x;
    float v1 = va.y + vf.y + vc.y + vb.y;
    v0 = v0 > 0.f ? v0 : 0.01f * v0;
    v1 = v1 > 0.f ? v1 : 0.01f * v1;

    ((float2*)(out + ((long)b * (E2 + NN) + e) * DD))[lane] = make_float2(v0, v1);

    float2 w = ((const float2*)w_attn)[lane];
    float dot = v0 * w.x + v1 * w.y;
    #pragma unroll
    for (int o = 16; o; o >>= 1) dot += __shfl_xor_sync(0xffffffffu, dot, o);

    float ev = expf(dot);
    if (lane == 0) { g_expl[gw] = ev; wred[warp] = ev; }
    __syncthreads();
    if (threadIdx.x < 16) {
        float v = wred[threadIdx.x];
        #pragma unroll
        for (int o = 8; o; o >>= 1) v += __shfl_xor_sync(0xffffu, v, o);
        if (threadIdx.x == 0) g_psum[blockIdx.x] = v;
    }
}

__global__ void sum_kernel(int pb)
{
    __shared__ float red[256];
    int b = blockIdx.x, tid = threadIdx.x;
    float s = 0.f;
    for (int j = tid; j < pb; j += 256) s += g_psum[b * pb + j];
    red[tid] = s; __syncthreads();
    for (int st = 128; st > 0; st >>= 1) {
        if (tid < st) red[tid] += red[tid + st];
        __syncthreads();
    }
    if (tid == 0) g_inv[b] = 1.0f / red[0];
}

__global__ void aggregate_kernel(const int* __restrict__ dst,
                                 float* __restrict__ out, int E2)
{
    int warp = threadIdx.x >> 5, lane = threadIdx.x & 31;
    int gw = blockIdx.x * 8 + warp;
    int b = gw / NN, n = gw - b * NN;
    int s0 = g_start[n], s1 = g_start[n + 1];
    float inv = g_inv[b];
    const float2* hb = (const float2*)(g_h + (long)b * NN * DD);
    const float*  ex = g_expl + (long)b * E2;
    float2 acc = make_float2(0.f, 0.f);
    for (int i = s0; i < s1; i++) {
        float a = ex[i] * inv;
        float2 hv = hb[(long)dst[i] * 32 + lane];
        acc.x += a * hv.x;
        acc.y += a * hv.y;
    }
    ((float2*)(out + ((long)b * (E2 + NN) + E2 + n) * DD))[lane] = acc;
}

// ---------------- launch ----------------
extern "C" void kernel_launch(void* const* d_in, const int* in_sizes, int n_in,
                              void* d_out, int out_size)
{
    const float* x      = (const float*)d_in[0];
    const float* W_edge = (const float*)d_in[1];
    const float* W_node = (const float*)d_in[2];
    const float* b_node = (const float*)d_in[3];
    const float* W_comb = (const float*)d_in[4];
    const float* b_comb = (const float*)d_in[5];
    const float* w_attn = (const float*)d_in[6];
    const int*   src    = (const int*)d_in[7];
    const int*   dst    = (const int*)d_in[8];
    const int*   eidx   = (const int*)d_in[9];
    const int    E2     = in_sizes[7];   // 16000
    float* out = (float*)d_out;

    cudaFuncSetAttribute(gemm_mma_kernel, cudaFuncAttributeMaxDynamicSharedMemorySize, SMEM_GEMM);

    prep_mm_kernel  <<<3, 256>>>(W_edge, W_node, W_comb);               // idx 0
    prep_bias_kernel<<<1, 128>>>(b_node, W_comb);                       // idx 1
    ranges_kernel   <<<8, 256>>>(src, E2);                              // idx 2
    gemm_mma_kernel <<<1750, 256, SMEM_GEMM>>>(x, W_node, b_node);      // idx 3 (profiled)
    edge_kernel     <<<BB * E2 / 16, 512>>>(b_comb, w_attn, src, dst, eidx, out, E2);
    sum_kernel      <<<BB, 256>>>(E2 / 16);
    aggregate_kernel<<<BB * NN / 8, 256>>>(dst, out, E2);
}